// round 10
// baseline (speedup 1.0000x reference)
#include <cuda_runtime.h>
#include <cuda.h>
#include <cuda_bf16.h>
#include <cstdint>

// Problem constants
#define PB   256      // batch
#define PE   512      // embed dim
#define PC   8192     // classes
#define PK   10       // centers per class
#define PN   (PC*PK)  // 81920 rows of fc
#define LMD        10.0f
#define INV_GAMMA  10.0f
#define TAU        0.2f
#define MARGIN     0.01f

// Scratch (static device globals; no allocation allowed)
__device__ __nv_bfloat16 g_wbf[(size_t)PN * PE];   // normalized centers, bf16 (84MB)
__device__ __nv_bfloat16 g_ebf[(size_t)PB * PE];   // emb bf16
__device__ float g_h[(size_t)PB * PC];             // soft-pooled class similarity
__device__ float g_regpart[PC];                    // per-class regularizer partial
__device__ float g_rowloss[PB];                    // per-batch-row CE loss
__device__ int   g_ctr = 0;                        // completion counter (self-resetting)

// ---------------------------------------------------------------------------
// PTX helpers (TMA / mbarrier / ldmatrix / mma.sync — all base sm_90+ PTX)
// ---------------------------------------------------------------------------
__device__ __forceinline__ uint32_t smem_u32(const void* p) {
    return (uint32_t)__cvta_generic_to_shared(p);
}
#define MBAR_INIT(a, n) \
    asm volatile("mbarrier.init.shared.b64 [%0], %1;" :: "r"(a), "r"(n) : "memory")
#define MBAR_EXPECT_TX(a, b) \
    asm volatile("mbarrier.arrive.expect_tx.shared.b64 _, [%0], %1;" :: "r"(a), "r"(b) : "memory")
__device__ __forceinline__ void mbar_wait(uint32_t mbar, uint32_t parity) {
    uint32_t done = 0;
    while (!done) {
        asm volatile(
            "{\n\t.reg .pred p;\n\t"
            "mbarrier.try_wait.parity.acquire.cta.shared::cta.b64 p, [%1], %2, 0x989680;\n\t"
            "selp.b32 %0, 1, 0, p;\n\t}"
            : "=r"(done) : "r"(mbar), "r"(parity) : "memory");
    }
}
#define TMA_LOAD_2D(smem, map, cx, cy, mbar) \
    asm volatile("cp.async.bulk.tensor.2d.shared::cta.global.tile.mbarrier::complete_tx::bytes " \
                 "[%0], [%1, {%2, %3}], [%4];" \
                 :: "r"(smem), "l"(map), "r"(cx), "r"(cy), "r"(mbar) : "memory")
#define FENCE_PROXY_ASYNC() asm volatile("fence.proxy.async.shared::cta;" ::: "memory")

__device__ __forceinline__ void ldsm_x4(uint32_t& r0, uint32_t& r1, uint32_t& r2, uint32_t& r3, uint32_t addr) {
    asm volatile("ldmatrix.sync.aligned.m8n8.x4.shared.b16 {%0,%1,%2,%3}, [%4];\n"
                 : "=r"(r0), "=r"(r1), "=r"(r2), "=r"(r3) : "r"(addr));
}
__device__ __forceinline__ void ldsm_x2(uint32_t& r0, uint32_t& r1, uint32_t addr) {
    asm volatile("ldmatrix.sync.aligned.m8n8.x2.shared.b16 {%0,%1}, [%2];\n"
                 : "=r"(r0), "=r"(r1) : "r"(addr));
}
__device__ __forceinline__ void mma16816(float* c, const uint32_t* a, const uint32_t* b) {
    asm volatile("mma.sync.aligned.m16n8k16.row.col.f32.bf16.bf16.f32 "
                 "{%0,%1,%2,%3}, {%4,%5,%6,%7}, {%8,%9}, {%0,%1,%2,%3};\n"
                 : "+f"(c[0]), "+f"(c[1]), "+f"(c[2]), "+f"(c[3])
                 : "r"(a[0]), "r"(a[1]), "r"(a[2]), "r"(a[3]), "r"(b[0]), "r"(b[1]));
}

// ---------------------------------------------------------------------------
// Kernel 1: per-class L2-norm (-> bf16) + register-blocked gram regularizer.
// Also converts 16 emb elements per block (absorbs former k_prep launch).
// Gram: warp a keeps row a in registers, streams rows b>a from smem
// (54 smem row-reads per block instead of 90 -> LDS-BW bound time drops).
// ---------------------------------------------------------------------------
__global__ void k_norm_reg(const float* __restrict__ fc, const float* __restrict__ emb)
{
    __shared__ float sw[10][PE];
    __shared__ float wpart[10];

    const int c    = blockIdx.x;
    const int warp = threadIdx.x >> 5;
    const int lane = threadIdx.x & 31;

    // absorbed k_prep: block c converts emb elements [c*16, c*16+16)
    if (threadIdx.x < 16) {
        const int i = c * 16 + threadIdx.x;   // 8192*16 = 131072 = PB*PE exactly
        g_ebf[i] = __float2bfloat16(emb[i]);
    }

    if (warp < 10) {
        const float* row = fc + ((size_t)c * PK + warp) * PE;
        float ss = 0.f;
#pragma unroll
        for (int q = 0; q < 4; q++) {
            float4 t = reinterpret_cast<const float4*>(row)[lane + 32 * q];
            reinterpret_cast<float4*>(&sw[warp][0])[lane + 32 * q] = t;
            ss += t.x * t.x + t.y * t.y + t.z * t.z + t.w * t.w;
        }
#pragma unroll
        for (int o = 16; o; o >>= 1) ss += __shfl_xor_sync(0xffffffffu, ss, o);
        const float inv = 1.0f / fmaxf(sqrtf(ss), 1e-12f);
        __nv_bfloat162* gw = reinterpret_cast<__nv_bfloat162*>(g_wbf + ((size_t)c * PK + warp) * PE);
#pragma unroll
        for (int q = 0; q < 4; q++) {
            float4 t = reinterpret_cast<float4*>(&sw[warp][0])[lane + 32 * q];
            t.x *= inv; t.y *= inv; t.z *= inv; t.w *= inv;
            reinterpret_cast<float4*>(&sw[warp][0])[lane + 32 * q] = t;
            gw[2 * (lane + 32 * q) + 0] = __floats2bfloat162_rn(t.x, t.y);
            gw[2 * (lane + 32 * q) + 1] = __floats2bfloat162_rn(t.z, t.w);
        }
    }
    __syncthreads();

    // register-blocked gram: warp a owns row a, streams rows b > a
    float acc = 0.f;
    const int a = warp;
    if (a < 9) {
        float4 ra[4];
#pragma unroll
        for (int q = 0; q < 4; q++)
            ra[q] = reinterpret_cast<const float4*>(&sw[a][0])[lane + 32 * q];
        for (int b = a + 1; b < 10; b++) {
            float d = 0.f;
#pragma unroll
            for (int q = 0; q < 4; q++) {
                float4 vb = reinterpret_cast<const float4*>(&sw[b][0])[lane + 32 * q];
                d += ra[q].x * vb.x + ra[q].y * vb.y + ra[q].z * vb.z + ra[q].w * vb.w;
            }
#pragma unroll
            for (int o = 16; o; o >>= 1) d += __shfl_xor_sync(0xffffffffu, d, o);
            float s = 1.0f - d;
            s = (s <= 0.f) ? 1e-10f : s;
            acc += sqrtf(2.0f * s);
        }
    }
    if (lane == 0) wpart[warp] = acc;   // warp 9 contributes 0
    __syncthreads();
    if (threadIdx.x == 0) {
        float t = 0.f;
#pragma unroll
        for (int i = 0; i < 10; i++) t += wpart[i];
        g_regpart[c] = t;
    }
}

// ---------------------------------------------------------------------------
// Kernel 2: GEMM x = e @ w.T via mma.sync, TMA-staged (SW128), fused softpool.
// Block 128(m) x 80(n); KSTAGE=64, 8 stages, 3-slot TMA ring; occupancy 2.
// 8 warps as 4(m) x 2(n); warp tile 32x40 (= 4 whole classes per warp).
// Fragment double-buffering hides ldsm latency under mma.
// ---------------------------------------------------------------------------
#define KSTAGE 64                       // 128B rows
#define NSTAGE (PE / KSTAGE)            // 8
#define NSLOT 3
#define NBLK  80
#define A_BYTES (128 * 128)             // 16384
#define B_BYTES (NBLK * 128)            // 10240
#define STG_BYTES (A_BYTES + B_BYTES)   // 26624
#define GSMEM (NSLOT * STG_BYTES + 1024)  // 80896

__global__ __launch_bounds__(256, 2) void k_gemm_mma(
    const __grid_constant__ CUtensorMap tma_a,
    const __grid_constant__ CUtensorMap tma_b)
{
    extern __shared__ char dsm_raw[];
    char* dsm = (char*)(((uintptr_t)dsm_raw + 1023) & ~(uintptr_t)1023);
    const uint32_t dsm_u = smem_u32(dsm);

    __shared__ uint64_t s_mbar[NSLOT];   // full barriers

    const int tid    = threadIdx.x;
    const int lane   = tid & 31;
    const int warp   = tid >> 5;
    const int warp_m = warp >> 1;      // 0..3
    const int warp_n = warp & 1;       // 0..1
    const int m0     = blockIdx.y * 128;
    const int n0     = blockIdx.x * NBLK;

    const uint32_t mb0 = smem_u32(&s_mbar[0]);

    if (tid == 0) {
#pragma unroll
        for (int s = 0; s < NSLOT; s++) MBAR_INIT(mb0 + 8 * s, 1);
    }
    __syncthreads();
    if (tid == 0) {
        FENCE_PROXY_ASYNC();
#pragma unroll
        for (int s = 0; s < NSLOT; s++) {
            MBAR_EXPECT_TX(mb0 + 8 * s, STG_BYTES);
            TMA_LOAD_2D(dsm_u + s * STG_BYTES,           &tma_a, s * KSTAGE, m0, mb0 + 8 * s);
            TMA_LOAD_2D(dsm_u + s * STG_BYTES + A_BYTES, &tma_b, s * KSTAGE, n0, mb0 + 8 * s);
        }
    }

    float acc[2][5][4];
#pragma unroll
    for (int i = 0; i < 2; i++)
#pragma unroll
        for (int j = 0; j < 5; j++)
#pragma unroll
            for (int r = 0; r < 4; r++) acc[i][j][r] = 0.f;

    // per-lane fragment rows (TMA SW128 swizzle: 16B-chunk ci -> ci ^ (row & 7))
    const int a_r  = lane & 15, a_sel = lane >> 4;          // ldsm_x4 A
    const int b_r  = lane & 7,  b_sel = (lane >> 3) & 1;    // ldsm_x2 B

    uint32_t af[2][2][4];   // [buf][mi][frag]
    uint32_t bfr[2][5][2];  // [buf][jn][frag]

    int ph[NSLOT] = {0, 0, 0};
    for (int t = 0; t < NSTAGE; t++) {
        const int s = t % NSLOT;
        mbar_wait(mb0 + 8 * s, ph[s]); ph[s] ^= 1;
        const uint32_t aBase = dsm_u + s * STG_BYTES;
        const uint32_t bBase = aBase + A_BYTES;

        // prime fragments for ks=0
        {
#pragma unroll
            for (int jn = 0; jn < 5; jn++) {
                const int row = warp_n * 40 + jn * 8 + b_r;
                ldsm_x2(bfr[0][jn][0], bfr[0][jn][1],
                        bBase + row * 128 + ((b_sel ^ (row & 7)) << 4));
            }
#pragma unroll
            for (int mi = 0; mi < 2; mi++) {
                const int row = warp_m * 32 + mi * 16 + a_r;
                ldsm_x4(af[0][mi][0], af[0][mi][1], af[0][mi][2], af[0][mi][3],
                        aBase + row * 128 + ((a_sel ^ (row & 7)) << 4));
            }
        }
#pragma unroll
        for (int ks = 0; ks < 4; ks++) {
            const int cur = ks & 1, nxt = cur ^ 1;
            if (ks < 3) {   // prefetch ks+1 fragments while mma on ks
#pragma unroll
                for (int jn = 0; jn < 5; jn++) {
                    const int row = warp_n * 40 + jn * 8 + b_r;
                    const int ci  = (ks + 1) * 2 + b_sel;
                    ldsm_x2(bfr[nxt][jn][0], bfr[nxt][jn][1],
                            bBase + row * 128 + ((ci ^ (row & 7)) << 4));
                }
#pragma unroll
                for (int mi = 0; mi < 2; mi++) {
                    const int row = warp_m * 32 + mi * 16 + a_r;
                    const int ci  = (ks + 1) * 2 + a_sel;
                    ldsm_x4(af[nxt][mi][0], af[nxt][mi][1], af[nxt][mi][2], af[nxt][mi][3],
                            aBase + row * 128 + ((ci ^ (row & 7)) << 4));
                }
            }
#pragma unroll
            for (int mi = 0; mi < 2; mi++)
#pragma unroll
                for (int jn = 0; jn < 5; jn++)
                    mma16816(acc[mi][jn], af[cur][mi], bfr[cur][jn]);
        }
        __syncthreads();
        if (tid == 0 && t + NSLOT < NSTAGE) {
            MBAR_EXPECT_TX(mb0 + 8 * s, STG_BYTES);
            TMA_LOAD_2D(dsm_u + s * STG_BYTES,           &tma_a, (t + NSLOT) * KSTAGE, m0, mb0 + 8 * s);
            TMA_LOAD_2D(dsm_u + s * STG_BYTES + A_BYTES, &tma_b, (t + NSLOT) * KSTAGE, n0, mb0 + 8 * s);
        }
    }

    // ---- epilogue: per m16 tile, transpose through smem, softpool K=10 ----
    float* xs = reinterpret_cast<float*>(dsm);
    float* xw = xs + warp * 640;   // [16][40] per warp
    const int cr = lane >> 2, cc = 2 * (lane & 3);
#pragma unroll
    for (int mi = 0; mi < 2; mi++) {
#pragma unroll
        for (int jn = 0; jn < 5; jn++) {
            xw[(cr + 0) * 40 + jn * 8 + cc + 0] = acc[mi][jn][0];
            xw[(cr + 0) * 40 + jn * 8 + cc + 1] = acc[mi][jn][1];
            xw[(cr + 8) * 40 + jn * 8 + cc + 0] = acc[mi][jn][2];
            xw[(cr + 8) * 40 + jn * 8 + cc + 1] = acc[mi][jn][3];
        }
        __syncwarp();
#pragma unroll
        for (int it = 0; it < 2; it++) {
            const int item = it * 32 + lane;
            const int row = item & 15, cls = item >> 4;   // cls 0..3
            const float* xp = xw + row * 40 + cls * 10;
            float mx = xp[0];
#pragma unroll
            for (int j = 1; j < 10; j++) mx = fmaxf(mx, xp[j]);
            float s = 0.f, hs = 0.f;
#pragma unroll
            for (int j = 0; j < 10; j++) {
                const float x = xp[j];
                const float e = __expf(INV_GAMMA * (x - mx));
                s += e; hs += e * x;
            }
            const int grow = m0 + warp_m * 32 + mi * 16 + row;
            const int gcls = blockIdx.x * 8 + warp_n * 4 + cls;
            g_h[(size_t)grow * PC + gcls] = hs / s;
        }
        __syncwarp();
    }
}

// ---------------------------------------------------------------------------
// Kernel 3: per-row CE (single pass, 512 threads x 16 logits in registers)
// + fused final reduction by the last block (deterministic fixed-order trees).
// ---------------------------------------------------------------------------
__global__ __launch_bounds__(512) void k_ce_final(const int* __restrict__ labels,
                                                  float* __restrict__ out)
{
    __shared__ float sred[512];
    __shared__ int sflag;
    const int b   = blockIdx.x;
    const int tid = threadIdx.x;
    const float* row = g_h + (size_t)b * PC;
    const int lab = labels[b];

    // one global pass: 16 strided logits per thread, kept in registers
    float v[16];
    float mx = -3.0e38f;
#pragma unroll
    for (int j = 0; j < 16; j++) {
        const int i = tid + 512 * j;
        v[j] = LMD * row[i] - ((i == lab) ? (LMD * MARGIN) : 0.f);
        mx = fmaxf(mx, v[j]);
    }
    sred[tid] = mx; __syncthreads();
    for (int o = 256; o; o >>= 1) {
        if (tid < o) sred[tid] = fmaxf(sred[tid], sred[tid + o]);
        __syncthreads();
    }
    mx = sred[0];
    __syncthreads();

    float s = 0.f;
#pragma unroll
    for (int j = 0; j < 16; j++) s += __expf(v[j] - mx);
    sred[tid] = s; __syncthreads();
    for (int o = 256; o; o >>= 1) {
        if (tid < o) sred[tid] += sred[tid + o];
        __syncthreads();
    }

    if (tid == 0) {
        const float vl = LMD * row[lab] - LMD * MARGIN;
        g_rowloss[b] = -(vl - mx - logf(sred[0]));
        __threadfence();
        const int old = atomicAdd(&g_ctr, 1);
        sflag = (old == PB - 1) ? 1 : 0;
    }
    __syncthreads();
    if (!sflag) return;

    // ---- last block: final deterministic reduction ----
    __threadfence();
    sred[tid] = (tid < PB) ? g_rowloss[tid] : 0.f;
    __syncthreads();
    for (int o = 256; o; o >>= 1) {
        if (tid < o) sred[tid] += sred[tid + o];
        __syncthreads();
    }
    const float losssum = sred[0];
    __syncthreads();

    float r = 0.f;
    for (int i = tid; i < PC; i += 512) r += g_regpart[i];
    sred[tid] = r; __syncthreads();
    for (int o = 256; o; o >>= 1) {
        if (tid < o) sred[tid] += sred[tid + o];
        __syncthreads();
    }
    if (tid == 0) {
        const float reg = sred[0] / ((float)PC * (float)(PK * (PK - 1)));
        out[0] = losssum / (float)PB + TAU * reg;
        g_ctr = 0;   // reset for next graph replay (deterministic)
    }
}

// ---------------------------------------------------------------------------
typedef CUresult (*EncodeFn)(CUtensorMap*, CUtensorMapDataType, cuuint32_t, void*,
                             const cuuint64_t*, const cuuint64_t*, const cuuint32_t*,
                             const cuuint32_t*, CUtensorMapInterleave, CUtensorMapSwizzle,
                             CUtensorMapL2promotion, CUtensorMapFloatOOBfill);

extern "C" void kernel_launch(void* const* d_in, const int* in_sizes, int n_in,
                              void* d_out, int out_size)
{
    (void)in_sizes; (void)n_in; (void)out_size;
    const float* emb    = (const float*)d_in[0];
    const int*   labels = (const int*)d_in[1];
    const float* fc     = (const float*)d_in[2];
    float*       out    = (float*)d_out;

    // Build TMA descriptors (host-side driver call via runtime entry point; no alloc)
    void* encode_raw = nullptr;
    cudaDriverEntryPointQueryResult qr;
    cudaGetDriverEntryPoint("cuTensorMapEncodeTiled", &encode_raw, cudaEnableDefault, &qr);
    EncodeFn encode = (EncodeFn)encode_raw;

    void *ebf_dev = nullptr, *wbf_dev = nullptr;
    cudaGetSymbolAddress(&ebf_dev, g_ebf);
    cudaGetSymbolAddress(&wbf_dev, g_wbf);

    CUtensorMap tma_a{}, tma_b{};
    {
        cuuint64_t dims[2]    = {PE, PB};
        cuuint64_t strides[1] = {PE * 2};
        cuuint32_t box[2]     = {KSTAGE, 128};
        cuuint32_t estr[2]    = {1, 1};
        encode(&tma_a, CU_TENSOR_MAP_DATA_TYPE_BFLOAT16, 2, ebf_dev,
               dims, strides, box, estr, CU_TENSOR_MAP_INTERLEAVE_NONE,
               CU_TENSOR_MAP_SWIZZLE_128B, CU_TENSOR_MAP_L2_PROMOTION_L2_128B,
               CU_TENSOR_MAP_FLOAT_OOB_FILL_NONE);
    }
    {
        cuuint64_t dims[2]    = {PE, PN};
        cuuint64_t strides[1] = {PE * 2};
        cuuint32_t box[2]     = {KSTAGE, NBLK};
        cuuint32_t estr[2]    = {1, 1};
        encode(&tma_b, CU_TENSOR_MAP_DATA_TYPE_BFLOAT16, 2, wbf_dev,
               dims, strides, box, estr, CU_TENSOR_MAP_INTERLEAVE_NONE,
               CU_TENSOR_MAP_SWIZZLE_128B, CU_TENSOR_MAP_L2_PROMOTION_L2_128B,
               CU_TENSOR_MAP_FLOAT_OOB_FILL_NONE);
    }

    cudaFuncSetAttribute(k_gemm_mma, cudaFuncAttributeMaxDynamicSharedMemorySize, GSMEM);

    k_norm_reg<<<PC, 320>>>(fc, emb);
    k_gemm_mma<<<dim3(PN / NBLK, PB / 128), 256, GSMEM>>>(tma_a, tma_b);
    k_ce_final<<<PB, 512>>>(labels, out);
}

// round 11
// speedup vs baseline: 1.1410x; 1.1410x over previous
#include <cuda_runtime.h>
#include <cuda.h>
#include <cuda_bf16.h>
#include <cstdint>

// Problem constants
#define PB   256      // batch
#define PE   512      // embed dim
#define PC   8192     // classes
#define PK   10       // centers per class
#define PN   (PC*PK)  // 81920 rows of fc
#define LMD        10.0f
#define INV_GAMMA  10.0f
#define TAU        0.2f
#define MARGIN     0.01f

// Scratch (static device globals; no allocation allowed)
__device__ __nv_bfloat16 g_wbf[(size_t)PN * PE];   // normalized centers, bf16 (84MB)
__device__ __nv_bfloat16 g_ebf[(size_t)PB * PE];   // emb bf16
__device__ float g_h[(size_t)PB * PC];             // soft-pooled class similarity
__device__ float g_regpart[PC];                    // per-class regularizer partial
__device__ float g_rowloss[PB];                    // per-batch-row CE loss
__device__ int   g_ctr = 0;                        // completion counter (self-resetting)

// ---------------------------------------------------------------------------
// PTX helpers (TMA / mbarrier / ldmatrix / mma.sync — all base sm_90+ PTX)
// ---------------------------------------------------------------------------
__device__ __forceinline__ uint32_t smem_u32(const void* p) {
    return (uint32_t)__cvta_generic_to_shared(p);
}
#define MBAR_INIT(a, n) \
    asm volatile("mbarrier.init.shared.b64 [%0], %1;" :: "r"(a), "r"(n) : "memory")
#define MBAR_EXPECT_TX(a, b) \
    asm volatile("mbarrier.arrive.expect_tx.shared.b64 _, [%0], %1;" :: "r"(a), "r"(b) : "memory")
__device__ __forceinline__ void mbar_wait(uint32_t mbar, uint32_t parity) {
    uint32_t done = 0;
    while (!done) {
        asm volatile(
            "{\n\t.reg .pred p;\n\t"
            "mbarrier.try_wait.parity.acquire.cta.shared::cta.b64 p, [%1], %2, 0x989680;\n\t"
            "selp.b32 %0, 1, 0, p;\n\t}"
            : "=r"(done) : "r"(mbar), "r"(parity) : "memory");
    }
}
#define TMA_LOAD_2D(smem, map, cx, cy, mbar) \
    asm volatile("cp.async.bulk.tensor.2d.shared::cta.global.tile.mbarrier::complete_tx::bytes " \
                 "[%0], [%1, {%2, %3}], [%4];" \
                 :: "r"(smem), "l"(map), "r"(cx), "r"(cy), "r"(mbar) : "memory")
#define FENCE_PROXY_ASYNC() asm volatile("fence.proxy.async.shared::cta;" ::: "memory")

__device__ __forceinline__ void ldsm_x4(uint32_t& r0, uint32_t& r1, uint32_t& r2, uint32_t& r3, uint32_t addr) {
    asm volatile("ldmatrix.sync.aligned.m8n8.x4.shared.b16 {%0,%1,%2,%3}, [%4];\n"
                 : "=r"(r0), "=r"(r1), "=r"(r2), "=r"(r3) : "r"(addr));
}
__device__ __forceinline__ void ldsm_x2(uint32_t& r0, uint32_t& r1, uint32_t addr) {
    asm volatile("ldmatrix.sync.aligned.m8n8.x2.shared.b16 {%0,%1}, [%2];\n"
                 : "=r"(r0), "=r"(r1) : "r"(addr));
}
__device__ __forceinline__ void mma16816(float* c, const uint32_t* a, const uint32_t* b) {
    asm volatile("mma.sync.aligned.m16n8k16.row.col.f32.bf16.bf16.f32 "
                 "{%0,%1,%2,%3}, {%4,%5,%6,%7}, {%8,%9}, {%0,%1,%2,%3};\n"
                 : "+f"(c[0]), "+f"(c[1]), "+f"(c[2]), "+f"(c[3])
                 : "r"(a[0]), "r"(a[1]), "r"(a[2]), "r"(a[3]), "r"(b[0]), "r"(b[1]));
}

// ---------------------------------------------------------------------------
// Kernel 1: per-class L2-norm (registers -> bf16 gmem + smem) + tensor-core
// gram regularizer (mma.sync 16x16x512, K-split over warps 0-3).
// Also converts 16 emb elements per block (absorbed k_prep).
// ---------------------------------------------------------------------------
#define SBF_PITCH 520   // bf16 elems per smem row: 1040B = 65 chunks -> conflict-free ldsm

__global__ void k_norm_reg(const float* __restrict__ fc, const float* __restrict__ emb)
{
    __shared__ alignas(16) __nv_bfloat16 sbf[16 * SBF_PITCH];  // 16 rows (10 live)
    __shared__ float pacc[4][16][16];                           // per-warp gram partials

    const int c    = blockIdx.x;
    const int warp = threadIdx.x >> 5;
    const int lane = threadIdx.x & 31;

    // absorbed k_prep: block c converts emb elements [c*16, c*16+16)
    if (threadIdx.x < 16) {
        const int i = c * 16 + threadIdx.x;   // 8192*16 = PB*PE exactly
        g_ebf[i] = __float2bfloat16(emb[i]);
    }

    // ---- normalization: registers only, write bf16 to gmem + smem ----
    if (warp < 10) {
        const float* row = fc + ((size_t)c * PK + warp) * PE;
        float4 t[4];
        float ss = 0.f;
#pragma unroll
        for (int q = 0; q < 4; q++) {
            t[q] = reinterpret_cast<const float4*>(row)[lane + 32 * q];
            ss += t[q].x * t[q].x + t[q].y * t[q].y + t[q].z * t[q].z + t[q].w * t[q].w;
        }
#pragma unroll
        for (int o = 16; o; o >>= 1) ss += __shfl_xor_sync(0xffffffffu, ss, o);
        const float inv = 1.0f / fmaxf(sqrtf(ss), 1e-12f);
        uint2* gw = reinterpret_cast<uint2*>(g_wbf + ((size_t)c * PK + warp) * PE);
        uint2* sw = reinterpret_cast<uint2*>(sbf + warp * SBF_PITCH);
#pragma unroll
        for (int q = 0; q < 4; q++) {
            __nv_bfloat162 lo = __floats2bfloat162_rn(t[q].x * inv, t[q].y * inv);
            __nv_bfloat162 hi = __floats2bfloat162_rn(t[q].z * inv, t[q].w * inv);
            uint2 v;
            v.x = *reinterpret_cast<uint32_t*>(&lo);
            v.y = *reinterpret_cast<uint32_t*>(&hi);
            gw[lane + 32 * q] = v;
            sw[lane + 32 * q] = v;
        }
    }
    __syncthreads();

    // ---- gram via mma.sync: warps 0-3 each cover 8 k16-steps ----
    if (warp < 4) {
        float g0[4] = {0.f, 0.f, 0.f, 0.f};
        float g1[4] = {0.f, 0.f, 0.f, 0.f};
        const uint32_t base = smem_u32(sbf);
        const int ar = lane & 15, asel = lane >> 4;
        const int br = lane & 7,  bsel = (lane >> 3) & 1;
#pragma unroll
        for (int j = 0; j < 8; j++) {
            const int ks = warp * 8 + j;
            uint32_t a[4];
            ldsm_x4(a[0], a[1], a[2], a[3], base + ar * 1040 + ks * 32 + asel * 16);
            uint32_t b0[2], b1[2];
            ldsm_x2(b0[0], b0[1], base + br * 1040 + ks * 32 + bsel * 16);
            ldsm_x2(b1[0], b1[1], base + (8 + br) * 1040 + ks * 32 + bsel * 16);
            mma16816(g0, a, b0);
            mma16816(g1, a, b1);
        }
        const int g = lane >> 2, t2 = lane & 3;
        pacc[warp][g    ][2 * t2    ] = g0[0];
        pacc[warp][g    ][2 * t2 + 1] = g0[1];
        pacc[warp][g + 8][2 * t2    ] = g0[2];
        pacc[warp][g + 8][2 * t2 + 1] = g0[3];
        pacc[warp][g    ][8 + 2 * t2    ] = g1[0];
        pacc[warp][g    ][8 + 2 * t2 + 1] = g1[1];
        pacc[warp][g + 8][8 + 2 * t2    ] = g1[2];
        pacc[warp][g + 8][8 + 2 * t2 + 1] = g1[3];
    }
    __syncthreads();

    // ---- warp 0: sum K-partials, strict-upper-triangle contributions ----
    if (warp == 0) {
        const int g = lane >> 2, t2 = lane & 3;
        float acc = 0.f;
#pragma unroll
        for (int rr = 0; rr < 2; rr++) {
            const int r = g + rr * 8;
#pragma unroll
            for (int cc = 0; cc < 4; cc++) {
                const int col = (cc & 1) + 2 * t2 + (cc >> 1) * 8;
                if (r < 10 && col < 10 && col > r) {
                    const float gv = pacc[0][r][col] + pacc[1][r][col]
                                   + pacc[2][r][col] + pacc[3][r][col];
                    float s = 1.0f - gv;
                    s = (s <= 0.f) ? 1e-10f : s;
                    acc += sqrtf(2.0f * s);
                }
            }
        }
#pragma unroll
        for (int o = 16; o; o >>= 1) acc += __shfl_xor_sync(0xffffffffu, acc, o);
        if (lane == 0) g_regpart[c] = acc;
    }
}

// ---------------------------------------------------------------------------
// Kernel 2: GEMM x = e @ w.T via mma.sync, TMA-staged (SW128), fused softpool.
// Block 128(m) x 80(n); KSTAGE=64, 8 stages, 3-slot TMA ring; occupancy 2.
// 8 warps as 4(m) x 2(n); warp tile 32x40 (= 4 whole classes per warp).
// ---------------------------------------------------------------------------
#define KSTAGE 64                       // 128B rows
#define NSTAGE (PE / KSTAGE)            // 8
#define NSLOT 3
#define NBLK  80
#define A_BYTES (128 * 128)             // 16384
#define B_BYTES (NBLK * 128)            // 10240
#define STG_BYTES (A_BYTES + B_BYTES)   // 26624
#define GSMEM (NSLOT * STG_BYTES + 1024)  // 80896

__global__ __launch_bounds__(256, 2) void k_gemm_mma(
    const __grid_constant__ CUtensorMap tma_a,
    const __grid_constant__ CUtensorMap tma_b)
{
    extern __shared__ char dsm_raw[];
    char* dsm = (char*)(((uintptr_t)dsm_raw + 1023) & ~(uintptr_t)1023);
    const uint32_t dsm_u = smem_u32(dsm);

    __shared__ uint64_t s_mbar[NSLOT];   // full barriers

    const int tid    = threadIdx.x;
    const int lane   = tid & 31;
    const int warp   = tid >> 5;
    const int warp_m = warp >> 1;      // 0..3
    const int warp_n = warp & 1;       // 0..1
    const int m0     = blockIdx.y * 128;
    const int n0     = blockIdx.x * NBLK;

    const uint32_t mb0 = smem_u32(&s_mbar[0]);

    if (tid == 0) {
#pragma unroll
        for (int s = 0; s < NSLOT; s++) MBAR_INIT(mb0 + 8 * s, 1);
    }
    __syncthreads();
    if (tid == 0) {
        FENCE_PROXY_ASYNC();
#pragma unroll
        for (int s = 0; s < NSLOT; s++) {
            MBAR_EXPECT_TX(mb0 + 8 * s, STG_BYTES);
            TMA_LOAD_2D(dsm_u + s * STG_BYTES,           &tma_a, s * KSTAGE, m0, mb0 + 8 * s);
            TMA_LOAD_2D(dsm_u + s * STG_BYTES + A_BYTES, &tma_b, s * KSTAGE, n0, mb0 + 8 * s);
        }
    }

    float acc[2][5][4];
#pragma unroll
    for (int i = 0; i < 2; i++)
#pragma unroll
        for (int j = 0; j < 5; j++)
#pragma unroll
            for (int r = 0; r < 4; r++) acc[i][j][r] = 0.f;

    // per-lane fragment rows (TMA SW128 swizzle: 16B-chunk ci -> ci ^ (row & 7))
    const int a_r  = lane & 15, a_sel = lane >> 4;          // ldsm_x4 A
    const int b_r  = lane & 7,  b_sel = (lane >> 3) & 1;    // ldsm_x2 B

    uint32_t af[2][2][4];   // [buf][mi][frag]
    uint32_t bfr[2][5][2];  // [buf][jn][frag]

    int ph[NSLOT] = {0, 0, 0};
    for (int t = 0; t < NSTAGE; t++) {
        const int s = t % NSLOT;
        mbar_wait(mb0 + 8 * s, ph[s]); ph[s] ^= 1;
        const uint32_t aBase = dsm_u + s * STG_BYTES;
        const uint32_t bBase = aBase + A_BYTES;

        // prime fragments for ks=0
        {
#pragma unroll
            for (int jn = 0; jn < 5; jn++) {
                const int row = warp_n * 40 + jn * 8 + b_r;
                ldsm_x2(bfr[0][jn][0], bfr[0][jn][1],
                        bBase + row * 128 + ((b_sel ^ (row & 7)) << 4));
            }
#pragma unroll
            for (int mi = 0; mi < 2; mi++) {
                const int row = warp_m * 32 + mi * 16 + a_r;
                ldsm_x4(af[0][mi][0], af[0][mi][1], af[0][mi][2], af[0][mi][3],
                        aBase + row * 128 + ((a_sel ^ (row & 7)) << 4));
            }
        }
#pragma unroll
        for (int ks = 0; ks < 4; ks++) {
            const int cur = ks & 1, nxt = cur ^ 1;
            if (ks < 3) {   // prefetch ks+1 fragments while mma on ks
#pragma unroll
                for (int jn = 0; jn < 5; jn++) {
                    const int row = warp_n * 40 + jn * 8 + b_r;
                    const int ci  = (ks + 1) * 2 + b_sel;
                    ldsm_x2(bfr[nxt][jn][0], bfr[nxt][jn][1],
                            bBase + row * 128 + ((ci ^ (row & 7)) << 4));
                }
#pragma unroll
                for (int mi = 0; mi < 2; mi++) {
                    const int row = warp_m * 32 + mi * 16 + a_r;
                    const int ci  = (ks + 1) * 2 + a_sel;
                    ldsm_x4(af[nxt][mi][0], af[nxt][mi][1], af[nxt][mi][2], af[nxt][mi][3],
                            aBase + row * 128 + ((ci ^ (row & 7)) << 4));
                }
            }
#pragma unroll
            for (int mi = 0; mi < 2; mi++)
#pragma unroll
                for (int jn = 0; jn < 5; jn++)
                    mma16816(acc[mi][jn], af[cur][mi], bfr[cur][jn]);
        }
        __syncthreads();
        if (tid == 0 && t + NSLOT < NSTAGE) {
            MBAR_EXPECT_TX(mb0 + 8 * s, STG_BYTES);
            TMA_LOAD_2D(dsm_u + s * STG_BYTES,           &tma_a, (t + NSLOT) * KSTAGE, m0, mb0 + 8 * s);
            TMA_LOAD_2D(dsm_u + s * STG_BYTES + A_BYTES, &tma_b, (t + NSLOT) * KSTAGE, n0, mb0 + 8 * s);
        }
    }

    // ---- epilogue: per m16 tile, transpose through smem, softpool K=10 ----
    float* xs = reinterpret_cast<float*>(dsm);
    float* xw = xs + warp * 640;   // [16][40] per warp
    const int cr = lane >> 2, cc = 2 * (lane & 3);
#pragma unroll
    for (int mi = 0; mi < 2; mi++) {
#pragma unroll
        for (int jn = 0; jn < 5; jn++) {
            xw[(cr + 0) * 40 + jn * 8 + cc + 0] = acc[mi][jn][0];
            xw[(cr + 0) * 40 + jn * 8 + cc + 1] = acc[mi][jn][1];
            xw[(cr + 8) * 40 + jn * 8 + cc + 0] = acc[mi][jn][2];
            xw[(cr + 8) * 40 + jn * 8 + cc + 1] = acc[mi][jn][3];
        }
        __syncwarp();
#pragma unroll
        for (int it = 0; it < 2; it++) {
            const int item = it * 32 + lane;
            const int row = item & 15, cls = item >> 4;   // cls 0..3
            const float* xp = xw + row * 40 + cls * 10;
            float mx = xp[0];
#pragma unroll
            for (int j = 1; j < 10; j++) mx = fmaxf(mx, xp[j]);
            float s = 0.f, hs = 0.f;
#pragma unroll
            for (int j = 0; j < 10; j++) {
                const float x = xp[j];
                const float e = __expf(INV_GAMMA * (x - mx));
                s += e; hs += e * x;
            }
            const int grow = m0 + warp_m * 32 + mi * 16 + row;
            const int gcls = blockIdx.x * 8 + warp_n * 4 + cls;
            g_h[(size_t)grow * PC + gcls] = hs / s;
        }
        __syncwarp();
    }
}

// ---------------------------------------------------------------------------
// Kernel 3: per-row CE (single pass, 512 threads x 16 logits in registers)
// + fused final reduction by the last block (deterministic fixed-order trees).
// ---------------------------------------------------------------------------
__global__ __launch_bounds__(512) void k_ce_final(const int* __restrict__ labels,
                                                  float* __restrict__ out)
{
    __shared__ float sred[512];
    __shared__ int sflag;
    const int b   = blockIdx.x;
    const int tid = threadIdx.x;
    const float* row = g_h + (size_t)b * PC;
    const int lab = labels[b];

    float v[16];
    float mx = -3.0e38f;
#pragma unroll
    for (int j = 0; j < 16; j++) {
        const int i = tid + 512 * j;
        v[j] = LMD * row[i] - ((i == lab) ? (LMD * MARGIN) : 0.f);
        mx = fmaxf(mx, v[j]);
    }
    sred[tid] = mx; __syncthreads();
    for (int o = 256; o; o >>= 1) {
        if (tid < o) sred[tid] = fmaxf(sred[tid], sred[tid + o]);
        __syncthreads();
    }
    mx = sred[0];
    __syncthreads();

    float s = 0.f;
#pragma unroll
    for (int j = 0; j < 16; j++) s += __expf(v[j] - mx);
    sred[tid] = s; __syncthreads();
    for (int o = 256; o; o >>= 1) {
        if (tid < o) sred[tid] += sred[tid + o];
        __syncthreads();
    }

    if (tid == 0) {
        const float vl = LMD * row[lab] - LMD * MARGIN;
        g_rowloss[b] = -(vl - mx - logf(sred[0]));
        __threadfence();
        const int old = atomicAdd(&g_ctr, 1);
        sflag = (old == PB - 1) ? 1 : 0;
    }
    __syncthreads();
    if (!sflag) return;

    // ---- last block: final deterministic reduction ----
    __threadfence();
    sred[tid] = (tid < PB) ? g_rowloss[tid] : 0.f;
    __syncthreads();
    for (int o = 256; o; o >>= 1) {
        if (tid < o) sred[tid] += sred[tid + o];
        __syncthreads();
    }
    const float losssum = sred[0];
    __syncthreads();

    float r = 0.f;
    for (int i = tid; i < PC; i += 512) r += g_regpart[i];
    sred[tid] = r; __syncthreads();
    for (int o = 256; o; o >>= 1) {
        if (tid < o) sred[tid] += sred[tid + o];
        __syncthreads();
    }
    if (tid == 0) {
        const float reg = sred[0] / ((float)PC * (float)(PK * (PK - 1)));
        out[0] = losssum / (float)PB + TAU * reg;
        g_ctr = 0;   // reset for next graph replay (deterministic)
    }
}

// ---------------------------------------------------------------------------
typedef CUresult (*EncodeFn)(CUtensorMap*, CUtensorMapDataType, cuuint32_t, void*,
                             const cuuint64_t*, const cuuint64_t*, const cuuint32_t*,
                             const cuuint32_t*, CUtensorMapInterleave, CUtensorMapSwizzle,
                             CUtensorMapL2promotion, CUtensorMapFloatOOBfill);

extern "C" void kernel_launch(void* const* d_in, const int* in_sizes, int n_in,
                              void* d_out, int out_size)
{
    (void)in_sizes; (void)n_in; (void)out_size;
    const float* emb    = (const float*)d_in[0];
    const int*   labels = (const int*)d_in[1];
    const float* fc     = (const float*)d_in[2];
    float*       out    = (float*)d_out;

    // Build TMA descriptors (host-side driver call via runtime entry point; no alloc)
    void* encode_raw = nullptr;
    cudaDriverEntryPointQueryResult qr;
    cudaGetDriverEntryPoint("cuTensorMapEncodeTiled", &encode_raw, cudaEnableDefault, &qr);
    EncodeFn encode = (EncodeFn)encode_raw;

    void *ebf_dev = nullptr, *wbf_dev = nullptr;
    cudaGetSymbolAddress(&ebf_dev, g_ebf);
    cudaGetSymbolAddress(&wbf_dev, g_wbf);

    CUtensorMap tma_a{}, tma_b{};
    {
        cuuint64_t dims[2]    = {PE, PB};
        cuuint64_t strides[1] = {PE * 2};
        cuuint32_t box[2]     = {KSTAGE, 128};
        cuuint32_t estr[2]    = {1, 1};
        encode(&tma_a, CU_TENSOR_MAP_DATA_TYPE_BFLOAT16, 2, ebf_dev,
               dims, strides, box, estr, CU_TENSOR_MAP_INTERLEAVE_NONE,
               CU_TENSOR_MAP_SWIZZLE_128B, CU_TENSOR_MAP_L2_PROMOTION_L2_128B,
               CU_TENSOR_MAP_FLOAT_OOB_FILL_NONE);
    }
    {
        cuuint64_t dims[2]    = {PE, PN};
        cuuint64_t strides[1] = {PE * 2};
        cuuint32_t box[2]     = {KSTAGE, NBLK};
        cuuint32_t estr[2]    = {1, 1};
        encode(&tma_b, CU_TENSOR_MAP_DATA_TYPE_BFLOAT16, 2, wbf_dev,
               dims, strides, box, estr, CU_TENSOR_MAP_INTERLEAVE_NONE,
               CU_TENSOR_MAP_SWIZZLE_128B, CU_TENSOR_MAP_L2_PROMOTION_L2_128B,
               CU_TENSOR_MAP_FLOAT_OOB_FILL_NONE);
    }

    cudaFuncSetAttribute(k_gemm_mma, cudaFuncAttributeMaxDynamicSharedMemorySize, GSMEM);

    k_norm_reg<<<PC, 320>>>(fc, emb);
    k_gemm_mma<<<dim3(PN / NBLK, PB / 128), 256, GSMEM>>>(tma_a, tma_b);
    k_ce_final<<<PB, 512>>>(labels, out);
}

// round 13
// speedup vs baseline: 1.3453x; 1.1790x over previous
#include <cuda_runtime.h>
#include <cuda.h>
#include <cuda_bf16.h>
#include <cstdint>

// Problem constants
#define PB   256      // batch
#define PE   512      // embed dim
#define PC   8192     // classes
#define PK   10       // centers per class
#define PN   (PC*PK)  // 81920 rows of fc
#define LMD        10.0f
#define INV_GAMMA  10.0f
#define TAU        0.2f
#define MARGIN     0.01f

// Scratch (static device globals; no allocation allowed)
__device__ __nv_bfloat16 g_wbf[(size_t)PN * PE];   // normalized centers, bf16 (84MB)
__device__ __nv_bfloat16 g_ebf[(size_t)PB * PE];   // emb bf16
__device__ float g_h[(size_t)PB * PC];             // soft-pooled class similarity
__device__ float g_regpart[PC];                    // per-class regularizer partial
__device__ float g_rowloss[PB];                    // per-batch-row CE loss
__device__ int   g_ctr = 0;                        // completion counter (self-resetting)

// ---------------------------------------------------------------------------
// PTX helpers (TMA / mbarrier / ldmatrix / mma.sync — all base sm_90+ PTX)
// ---------------------------------------------------------------------------
__device__ __forceinline__ uint32_t smem_u32(const void* p) {
    return (uint32_t)__cvta_generic_to_shared(p);
}
#define MBAR_INIT(a, n) \
    asm volatile("mbarrier.init.shared.b64 [%0], %1;" :: "r"(a), "r"(n) : "memory")
#define MBAR_EXPECT_TX(a, b) \
    asm volatile("mbarrier.arrive.expect_tx.shared.b64 _, [%0], %1;" :: "r"(a), "r"(b) : "memory")
__device__ __forceinline__ void mbar_wait(uint32_t mbar, uint32_t parity) {
    uint32_t done = 0;
    while (!done) {
        asm volatile(
            "{\n\t.reg .pred p;\n\t"
            "mbarrier.try_wait.parity.acquire.cta.shared::cta.b64 p, [%1], %2, 0x989680;\n\t"
            "selp.b32 %0, 1, 0, p;\n\t}"
            : "=r"(done) : "r"(mbar), "r"(parity) : "memory");
    }
}
#define TMA_LOAD_2D(smem, map, cx, cy, mbar) \
    asm volatile("cp.async.bulk.tensor.2d.shared::cta.global.tile.mbarrier::complete_tx::bytes " \
                 "[%0], [%1, {%2, %3}], [%4];" \
                 :: "r"(smem), "l"(map), "r"(cx), "r"(cy), "r"(mbar) : "memory")
#define FENCE_PROXY_ASYNC() asm volatile("fence.proxy.async.shared::cta;" ::: "memory")

__device__ __forceinline__ void ldsm_x4(uint32_t& r0, uint32_t& r1, uint32_t& r2, uint32_t& r3, uint32_t addr) {
    asm volatile("ldmatrix.sync.aligned.m8n8.x4.shared.b16 {%0,%1,%2,%3}, [%4];\n"
                 : "=r"(r0), "=r"(r1), "=r"(r2), "=r"(r3) : "r"(addr));
}
__device__ __forceinline__ void ldsm_x2(uint32_t& r0, uint32_t& r1, uint32_t addr) {
    asm volatile("ldmatrix.sync.aligned.m8n8.x2.shared.b16 {%0,%1}, [%2];\n"
                 : "=r"(r0), "=r"(r1) : "r"(addr));
}
__device__ __forceinline__ void mma16816(float* c, const uint32_t* a, const uint32_t* b) {
    asm volatile("mma.sync.aligned.m16n8k16.row.col.f32.bf16.bf16.f32 "
                 "{%0,%1,%2,%3}, {%4,%5,%6,%7}, {%8,%9}, {%0,%1,%2,%3};\n"
                 : "+f"(c[0]), "+f"(c[1]), "+f"(c[2]), "+f"(c[3])
                 : "r"(a[0]), "r"(a[1]), "r"(a[2]), "r"(a[3]), "r"(b[0]), "r"(b[1]));
}

// ---------------------------------------------------------------------------
// Kernel 1: pure streaming L2-normalization. One warp = one w row. No smem,
// no syncthreads, no phases -> DRAM stays saturated. Blocks < 512 also
// convert 256 emb elements each (absorbed k_prep).
// ---------------------------------------------------------------------------
__global__ __launch_bounds__(256) void k_norm(const float* __restrict__ fc,
                                              const float* __restrict__ emb)
{
    const int warp = threadIdx.x >> 5;
    const int lane = threadIdx.x & 31;
    const int row  = blockIdx.x * 8 + warp;   // grid = PN/8 = 10240

    if (blockIdx.x < 512) {
        const int i = blockIdx.x * 256 + threadIdx.x;  // 512*256 = PB*PE exactly
        g_ebf[i] = __float2bfloat16(emb[i]);
    }

    const float* r = fc + (size_t)row * PE;
    float4 t[4];
    float ss = 0.f;
#pragma unroll
    for (int q = 0; q < 4; q++) {
        t[q] = reinterpret_cast<const float4*>(r)[lane + 32 * q];
        ss += t[q].x * t[q].x + t[q].y * t[q].y + t[q].z * t[q].z + t[q].w * t[q].w;
    }
#pragma unroll
    for (int o = 16; o; o >>= 1) ss += __shfl_xor_sync(0xffffffffu, ss, o);
    const float inv = 1.0f / fmaxf(sqrtf(ss), 1e-12f);
    uint2* gw = reinterpret_cast<uint2*>(g_wbf + (size_t)row * PE);
#pragma unroll
    for (int q = 0; q < 4; q++) {
        __nv_bfloat162 lo = __floats2bfloat162_rn(t[q].x * inv, t[q].y * inv);
        __nv_bfloat162 hi = __floats2bfloat162_rn(t[q].z * inv, t[q].w * inv);
        uint2 v;
        v.x = *reinterpret_cast<uint32_t*>(&lo);
        v.y = *reinterpret_cast<uint32_t*>(&hi);
        gw[lane + 32 * q] = v;
    }
}

// ---------------------------------------------------------------------------
// Kernel 2: GEMM x = e @ w.T via mma.sync, TMA-staged (SW128), fused softpool
// AND fused gram regularizer: y==0 blocks accumulate each class's 16x16 gram
// from the B tile already resident in smem (warp w <-> class w of this
// n-block), zero extra DRAM traffic. Block 128(m) x 80(n); 3-slot TMA ring.
// ---------------------------------------------------------------------------
#define KSTAGE 64                       // 128B rows
#define NSTAGE (PE / KSTAGE)            // 8
#define NSLOT 3
#define NBLK  80
#define A_BYTES (128 * 128)             // 16384
#define B_BYTES (NBLK * 128)            // 10240
#define STG_BYTES (A_BYTES + B_BYTES)   // 26624
#define GSMEM (NSLOT * STG_BYTES + 1024)  // 80896

__global__ __launch_bounds__(256, 2) void k_gemm_mma(
    const __grid_constant__ CUtensorMap tma_a,
    const __grid_constant__ CUtensorMap tma_b)
{
    extern __shared__ char dsm_raw[];
    char* dsm = (char*)(((uintptr_t)dsm_raw + 1023) & ~(uintptr_t)1023);
    const uint32_t dsm_u = smem_u32(dsm);

    __shared__ uint64_t s_mbar[NSLOT];   // full barriers

    const int tid    = threadIdx.x;
    const int lane   = tid & 31;
    const int warp   = tid >> 5;
    const int warp_m = warp >> 1;      // 0..3
    const int warp_n = warp & 1;       // 0..1
    const int m0     = blockIdx.y * 128;
    const int n0     = blockIdx.x * NBLK;
    const bool do_gram = (blockIdx.y == 0);

    const uint32_t mb0 = smem_u32(&s_mbar[0]);

    if (tid == 0) {
#pragma unroll
        for (int s = 0; s < NSLOT; s++) MBAR_INIT(mb0 + 8 * s, 1);
    }
    __syncthreads();
    if (tid == 0) {
        FENCE_PROXY_ASYNC();
#pragma unroll
        for (int s = 0; s < NSLOT; s++) {
            MBAR_EXPECT_TX(mb0 + 8 * s, STG_BYTES);
            TMA_LOAD_2D(dsm_u + s * STG_BYTES,           &tma_a, s * KSTAGE, m0, mb0 + 8 * s);
            TMA_LOAD_2D(dsm_u + s * STG_BYTES + A_BYTES, &tma_b, s * KSTAGE, n0, mb0 + 8 * s);
        }
    }

    float acc[2][5][4];
#pragma unroll
    for (int i = 0; i < 2; i++)
#pragma unroll
        for (int j = 0; j < 5; j++)
#pragma unroll
            for (int r = 0; r < 4; r++) acc[i][j][r] = 0.f;

    // gram accumulators (y==0): warp w owns class w of this n-block
    float ga0[4] = {0.f, 0.f, 0.f, 0.f};
    float ga1[4] = {0.f, 0.f, 0.f, 0.f};
    const int wbase = warp * 10;                        // local B row of class
    // clamped fragment rows (lanes feeding m/n >= 10 read row <= wbase+9; unused cells)
    const int g_ar  = (lane & 15) < 10 ? (lane & 15) : 9;
    const int g_br  = lane & 7;
    const int g_br2 = g_br < 2 ? g_br : 1;

    // per-lane fragment rows (TMA SW128 swizzle: 16B-chunk ci -> ci ^ (row & 7))
    const int a_r  = lane & 15, a_sel = lane >> 4;          // ldsm_x4 A
    const int b_r  = lane & 7,  b_sel = (lane >> 3) & 1;    // ldsm_x2 B

    uint32_t af[2][2][4];   // [buf][mi][frag]
    uint32_t bfr[2][5][2];  // [buf][jn][frag]

    int ph[NSLOT] = {0, 0, 0};
    for (int t = 0; t < NSTAGE; t++) {
        const int s = t % NSLOT;
        mbar_wait(mb0 + 8 * s, ph[s]); ph[s] ^= 1;
        const uint32_t aBase = dsm_u + s * STG_BYTES;
        const uint32_t bBase = aBase + A_BYTES;

        // prime fragments for ks=0
        {
#pragma unroll
            for (int jn = 0; jn < 5; jn++) {
                const int row = warp_n * 40 + jn * 8 + b_r;
                ldsm_x2(bfr[0][jn][0], bfr[0][jn][1],
                        bBase + row * 128 + ((b_sel ^ (row & 7)) << 4));
            }
#pragma unroll
            for (int mi = 0; mi < 2; mi++) {
                const int row = warp_m * 32 + mi * 16 + a_r;
                ldsm_x4(af[0][mi][0], af[0][mi][1], af[0][mi][2], af[0][mi][3],
                        aBase + row * 128 + ((a_sel ^ (row & 7)) << 4));
            }
        }
#pragma unroll
        for (int ks = 0; ks < 4; ks++) {
            const int cur = ks & 1, nxt = cur ^ 1;
            if (ks < 3) {   // prefetch ks+1 fragments while mma on ks
#pragma unroll
                for (int jn = 0; jn < 5; jn++) {
                    const int row = warp_n * 40 + jn * 8 + b_r;
                    const int ci  = (ks + 1) * 2 + b_sel;
                    ldsm_x2(bfr[nxt][jn][0], bfr[nxt][jn][1],
                            bBase + row * 128 + ((ci ^ (row & 7)) << 4));
                }
#pragma unroll
                for (int mi = 0; mi < 2; mi++) {
                    const int row = warp_m * 32 + mi * 16 + a_r;
                    const int ci  = (ks + 1) * 2 + a_sel;
                    ldsm_x4(af[nxt][mi][0], af[nxt][mi][1], af[nxt][mi][2], af[nxt][mi][3],
                            aBase + row * 128 + ((ci ^ (row & 7)) << 4));
                }
            }
#pragma unroll
            for (int mi = 0; mi < 2; mi++)
#pragma unroll
                for (int jn = 0; jn < 5; jn++)
                    mma16816(acc[mi][jn], af[cur][mi], bfr[cur][jn]);
        }

        // ---- fused gram: class w's 16x16 gram partial from the B tile ----
        if (do_gram) {
#pragma unroll
            for (int ks = 0; ks < 4; ks++) {
                uint32_t a[4], b0[2], b1[2];
                const int rowA  = wbase + g_ar;
                const int rowB0 = wbase + g_br;
                const int rowB1 = wbase + 8 + g_br2;
                const int ciA = ks * 2 + a_sel;
                const int ciB = ks * 2 + b_sel;
                ldsm_x4(a[0], a[1], a[2], a[3],
                        bBase + rowA * 128 + ((ciA ^ (rowA & 7)) << 4));
                ldsm_x2(b0[0], b0[1],
                        bBase + rowB0 * 128 + ((ciB ^ (rowB0 & 7)) << 4));
                ldsm_x2(b1[0], b1[1],
                        bBase + rowB1 * 128 + ((ciB ^ (rowB1 & 7)) << 4));
                mma16816(ga0, a, b0);
                mma16816(ga1, a, b1);
            }
        }
        __syncthreads();
        if (tid == 0 && t + NSLOT < NSTAGE) {
            MBAR_EXPECT_TX(mb0 + 8 * s, STG_BYTES);
            TMA_LOAD_2D(dsm_u + s * STG_BYTES,           &tma_a, (t + NSLOT) * KSTAGE, m0, mb0 + 8 * s);
            TMA_LOAD_2D(dsm_u + s * STG_BYTES + A_BYTES, &tma_b, (t + NSLOT) * KSTAGE, n0, mb0 + 8 * s);
        }
    }

    // ---- gram epilogue: extract 45 strict-upper-triangle cells ----
    if (do_gram) {
        const int g = lane >> 2, t2 = lane & 3;
        float racc = 0.f;
        const float gv[8] = {ga0[0], ga0[1], ga0[2], ga0[3], ga1[0], ga1[1], ga1[2], ga1[3]};
        const int rr[8]   = {g, g, g + 8, g + 8, g, g, g + 8, g + 8};
        const int cc[8]   = {2 * t2, 2 * t2 + 1, 2 * t2, 2 * t2 + 1,
                             8 + 2 * t2, 8 + 2 * t2 + 1, 8 + 2 * t2, 8 + 2 * t2 + 1};
#pragma unroll
        for (int q = 0; q < 8; q++) {
            if (rr[q] < 10 && cc[q] < 10 && cc[q] > rr[q]) {
                float s = 1.0f - gv[q];
                s = (s <= 0.f) ? 1e-10f : s;
                racc += sqrtf(2.0f * s);
            }
        }
#pragma unroll
        for (int o = 16; o; o >>= 1) racc += __shfl_xor_sync(0xffffffffu, racc, o);
        if (lane == 0) g_regpart[blockIdx.x * 8 + warp] = racc;
    }

    // ---- epilogue: per m16 tile, transpose through smem, softpool K=10 ----
    float* xs = reinterpret_cast<float*>(dsm);
    float* xw = xs + warp * 640;   // [16][40] per warp
    const int cr = lane >> 2, cc2 = 2 * (lane & 3);
#pragma unroll
    for (int mi = 0; mi < 2; mi++) {
#pragma unroll
        for (int jn = 0; jn < 5; jn++) {
            xw[(cr + 0) * 40 + jn * 8 + cc2 + 0] = acc[mi][jn][0];
            xw[(cr + 0) * 40 + jn * 8 + cc2 + 1] = acc[mi][jn][1];
            xw[(cr + 8) * 40 + jn * 8 + cc2 + 0] = acc[mi][jn][2];
            xw[(cr + 8) * 40 + jn * 8 + cc2 + 1] = acc[mi][jn][3];
        }
        __syncwarp();
#pragma unroll
        for (int it = 0; it < 2; it++) {
            const int item = it * 32 + lane;
            const int row = item & 15, cls = item >> 4;   // cls 0..3
            const float* xp = xw + row * 40 + cls * 10;
            float mx = xp[0];
#pragma unroll
            for (int j = 1; j < 10; j++) mx = fmaxf(mx, xp[j]);
            float s = 0.f, hs = 0.f;
#pragma unroll
            for (int j = 0; j < 10; j++) {
                const float x = xp[j];
                const float e = __expf(INV_GAMMA * (x - mx));
                s += e; hs += e * x;
            }
            const int grow = m0 + warp_m * 32 + mi * 16 + row;
            const int gcls = blockIdx.x * 8 + warp_n * 4 + cls;
            g_h[(size_t)grow * PC + gcls] = hs / s;
        }
        __syncwarp();
    }
}

// ---------------------------------------------------------------------------
// Kernel 3: per-row CE (single pass, 512 threads x 16 logits in registers)
// + fused final reduction by the last block (deterministic fixed-order trees).
// ---------------------------------------------------------------------------
__global__ __launch_bounds__(512) void k_ce_final(const int* __restrict__ labels,
                                                  float* __restrict__ out)
{
    __shared__ float sred[512];
    __shared__ int sflag;
    const int b   = blockIdx.x;
    const int tid = threadIdx.x;
    const float* row = g_h + (size_t)b * PC;
    const int lab = labels[b];

    float v[16];
    float mx = -3.0e38f;
#pragma unroll
    for (int j = 0; j < 16; j++) {
        const int i = tid + 512 * j;
        v[j] = LMD * row[i] - ((i == lab) ? (LMD * MARGIN) : 0.f);
        mx = fmaxf(mx, v[j]);
    }
    sred[tid] = mx; __syncthreads();
    for (int o = 256; o; o >>= 1) {
        if (tid < o) sred[tid] = fmaxf(sred[tid], sred[tid + o]);
        __syncthreads();
    }
    mx = sred[0];
    __syncthreads();

    float s = 0.f;
#pragma unroll
    for (int j = 0; j < 16; j++) s += __expf(v[j] - mx);
    sred[tid] = s; __syncthreads();
    for (int o = 256; o; o >>= 1) {
        if (tid < o) sred[tid] += sred[tid + o];
        __syncthreads();
    }

    if (tid == 0) {
        const float vl = LMD * row[lab] - LMD * MARGIN;
        g_rowloss[b] = -(vl - mx - logf(sred[0]));
        __threadfence();
        const int old = atomicAdd(&g_ctr, 1);
        sflag = (old == PB - 1) ? 1 : 0;
    }
    __syncthreads();
    if (!sflag) return;

    // ---- last block: final deterministic reduction ----
    __threadfence();
    sred[tid] = (tid < PB) ? g_rowloss[tid] : 0.f;
    __syncthreads();
    for (int o = 256; o; o >>= 1) {
        if (tid < o) sred[tid] += sred[tid + o];
        __syncthreads();
    }
    const float losssum = sred[0];
    __syncthreads();

    float r = 0.f;
    for (int i = tid; i < PC; i += 512) r += g_regpart[i];
    sred[tid] = r; __syncthreads();
    for (int o = 256; o; o >>= 1) {
        if (tid < o) sred[tid] += sred[tid + o];
        __syncthreads();
    }
    if (tid == 0) {
        const float reg = sred[0] / ((float)PC * (float)(PK * (PK - 1)));
        out[0] = losssum / (float)PB + TAU * reg;
        g_ctr = 0;   // reset for next graph replay (deterministic)
    }
}

// ---------------------------------------------------------------------------
typedef CUresult (*EncodeFn)(CUtensorMap*, CUtensorMapDataType, cuuint32_t, void*,
                             const cuuint64_t*, const cuuint64_t*, const cuuint32_t*,
                             const cuuint32_t*, CUtensorMapInterleave, CUtensorMapSwizzle,
                             CUtensorMapL2promotion, CUtensorMapFloatOOBfill);

extern "C" void kernel_launch(void* const* d_in, const int* in_sizes, int n_in,
                              void* d_out, int out_size)
{
    (void)in_sizes; (void)n_in; (void)out_size;
    const float* emb    = (const float*)d_in[0];
    const int*   labels = (const int*)d_in[1];
    const float* fc     = (const float*)d_in[2];
    float*       out    = (float*)d_out;

    // Build TMA descriptors (host-side driver call via runtime entry point; no alloc)
    void* encode_raw = nullptr;
    cudaDriverEntryPointQueryResult qr;
    cudaGetDriverEntryPoint("cuTensorMapEncodeTiled", &encode_raw, cudaEnableDefault, &qr);
    EncodeFn encode = (EncodeFn)encode_raw;

    void *ebf_dev = nullptr, *wbf_dev = nullptr;
    cudaGetSymbolAddress(&ebf_dev, g_ebf);
    cudaGetSymbolAddress(&wbf_dev, g_wbf);

    CUtensorMap tma_a{}, tma_b{};
    {
        cuuint64_t dims[2]    = {PE, PB};
        cuuint64_t strides[1] = {PE * 2};
        cuuint32_t box[2]     = {KSTAGE, 128};
        cuuint32_t estr[2]    = {1, 1};
        encode(&tma_a, CU_TENSOR_MAP_DATA_TYPE_BFLOAT16, 2, ebf_dev,
               dims, strides, box, estr, CU_TENSOR_MAP_INTERLEAVE_NONE,
               CU_TENSOR_MAP_SWIZZLE_128B, CU_TENSOR_MAP_L2_PROMOTION_L2_128B,
               CU_TENSOR_MAP_FLOAT_OOB_FILL_NONE);
    }
    {
        cuuint64_t dims[2]    = {PE, PN};
        cuuint64_t strides[1] = {PE * 2};
        cuuint32_t box[2]     = {KSTAGE, NBLK};
        cuuint32_t estr[2]    = {1, 1};
        encode(&tma_b, CU_TENSOR_MAP_DATA_TYPE_BFLOAT16, 2, wbf_dev,
               dims, strides, box, estr, CU_TENSOR_MAP_INTERLEAVE_NONE,
               CU_TENSOR_MAP_SWIZZLE_128B, CU_TENSOR_MAP_L2_PROMOTION_L2_128B,
               CU_TENSOR_MAP_FLOAT_OOB_FILL_NONE);
    }

    cudaFuncSetAttribute(k_gemm_mma, cudaFuncAttributeMaxDynamicSharedMemorySize, GSMEM);

    k_norm<<<PN / 8, 256>>>(fc, emb);
    k_gemm_mma<<<dim3(PN / NBLK, PB / 128), 256, GSMEM>>>(tma_a, tma_b);
    k_ce_final<<<PB, 512>>>(labels, out);
}